// round 7
// baseline (speedup 1.0000x reference)
#include <cuda_runtime.h>
#include <cuda_bf16.h>
#include <cstdint>

// GCN forward: 4x (mma.sync bf16x3 GEMM + CSR-gather) + segmented pool + fused MLP.
// Single stream (fork regressed: 1-block scan starved under concurrent GEMM).
// GEMM tile 64x128, smem 104KB -> 2 CTAs/SM.

#define DD 128
#define NMAX 50000
#define EMAX 800000
#define GMAX 512

__device__ int   g_is64;
__device__ float g_h[NMAX * DD];
__device__ float g_hw[NMAX * DD];
__device__ float g_dinv[NMAX];
__device__ float g_self[NMAX];
__device__ int   g_hist[NMAX];
__device__ int   g_rowstart[NMAX + 1];
__device__ int   g_cursor[NMAX];
__device__ int   g_csrc[EMAX];
__device__ float g_cw[EMAX];
__device__ float g_pool[GMAX * DD];
__device__ __nv_bfloat16 g_Wbf[4][2][DD * DD];

__device__ __forceinline__ uint32_t smem_u32(const void* p) {
    return (uint32_t)__cvta_generic_to_shared(p);
}
__device__ __forceinline__ long long idx_at(const void* p, long long i) {
    if (g_is64) return ((const long long*)p)[i];
    return (long long)((const int*)p)[i];
}

__global__ void detect_kernel(const unsigned int* __restrict__ p) {
    if (threadIdx.x == 0 && blockIdx.x == 0) {
        int is64 = 1;
        for (int k = 1; k <= 15; k += 2)
            if (p[k] != 0u) { is64 = 0; break; }
        g_is64 = is64;
    }
}

__global__ void zero_hist_kernel(int n) {
    int i = blockIdx.x * blockDim.x + threadIdx.x;
    if (i < n) g_hist[i] = 0;
}

__global__ void hist_kernel(const void* __restrict__ ei, int E) {
    int e = blockIdx.x * blockDim.x + threadIdx.x;
    if (e < E) {
        int c = (int)idx_at(ei, (long long)E + e);
        atomicAdd(&g_hist[c], 1);
    }
}

__global__ void dinv_kernel(int n) {
    int i = blockIdx.x * blockDim.x + threadIdx.x;
    if (i < n) {
        float deg = (float)g_hist[i] + 1.0f;
        g_dinv[i] = rsqrtf(deg);
        g_self[i] = 1.0f / deg;
    }
}

__global__ void scan_kernel(int n, int E) {
    __shared__ int sums[1024];
    int t = threadIdx.x;
    int chunk = (n + 1023) / 1024;
    int b0 = t * chunk;
    int b1 = min(b0 + chunk, n);
    int s = 0;
    for (int i = b0; i < b1; i++) s += g_hist[i];
    sums[t] = s;
    __syncthreads();
    for (int off = 1; off < 1024; off <<= 1) {
        int v = (t >= off) ? sums[t - off] : 0;
        __syncthreads();
        sums[t] += v;
        __syncthreads();
    }
    int run = (t == 0) ? 0 : sums[t - 1];
    for (int i = b0; i < b1; i++) {
        g_rowstart[i] = run;
        g_cursor[i] = run;
        run += g_hist[i];
    }
    if (t == 0) g_rowstart[n] = E;
}

__global__ void fill_kernel(const void* __restrict__ ei, int E) {
    int e = blockIdx.x * blockDim.x + threadIdx.x;
    if (e < E) {
        int r = (int)idx_at(ei, e);
        int c = (int)idx_at(ei, (long long)E + e);
        int pos = atomicAdd(&g_cursor[c], 1);
        g_csrc[pos] = r;
        g_cw[pos] = g_dinv[r] * g_dinv[c];
    }
}

__global__ void prep_w_kernel(const float* __restrict__ W_conv, int n_layers) {
    int idx = blockIdx.x * blockDim.x + threadIdx.x;
    int total = n_layers * DD * DD;
    if (idx >= total) return;
    int l = idx / (DD * DD);
    int rem = idx % (DD * DD);
    int k = rem / DD;
    int n = rem % DD;
    float w = W_conv[(long long)l * DD * DD + k * DD + n];
    __nv_bfloat16 hi = __float2bfloat16(w);
    __nv_bfloat16 lo = __float2bfloat16(w - __bfloat162float(hi));
    g_Wbf[l][0][n * DD + k] = hi;
    g_Wbf[l][1][n * DD + k] = lo;
}

// ---------------- mma.sync bf16x3 GEMM: tile 64(M) x 128(N), K=128 ----------------
#define ASTR 136
#define A_TILE_B (64 * ASTR * 2)      // 17408
#define B_TILE_B (128 * ASTR * 2)     // 34816
#define SM_AH 0
#define SM_AL (A_TILE_B)
#define SM_BH (2 * A_TILE_B)
#define SM_BL (2 * A_TILE_B + B_TILE_B)
#define SM_TOTAL (2 * A_TILE_B + 2 * B_TILE_B)   // 104448

__device__ __forceinline__ void ldmat_x4(uint32_t* r, uint32_t addr) {
    asm volatile("ldmatrix.sync.aligned.m8n8.x4.shared.b16 {%0,%1,%2,%3}, [%4];"
                 : "=r"(r[0]), "=r"(r[1]), "=r"(r[2]), "=r"(r[3]) : "r"(addr));
}
__device__ __forceinline__ void ldmat_x2(uint32_t* r, uint32_t addr) {
    asm volatile("ldmatrix.sync.aligned.m8n8.x2.shared.b16 {%0,%1}, [%2];"
                 : "=r"(r[0]), "=r"(r[1]) : "r"(addr));
}
__device__ __forceinline__ void mma_bf16(float* c, const uint32_t* a, const uint32_t* b) {
    asm volatile("mma.sync.aligned.m16n8k16.row.col.f32.bf16.bf16.f32 "
                 "{%0,%1,%2,%3}, {%4,%5,%6,%7}, {%8,%9}, {%0,%1,%2,%3};"
                 : "+f"(c[0]), "+f"(c[1]), "+f"(c[2]), "+f"(c[3])
                 : "r"(a[0]), "r"(a[1]), "r"(a[2]), "r"(a[3]), "r"(b[0]), "r"(b[1]));
}

__global__ void __launch_bounds__(256, 2)
gemm_mma_kernel(const float* __restrict__ A,
                const __nv_bfloat16* __restrict__ Whi,
                const __nv_bfloat16* __restrict__ Wlo,
                float* __restrict__ C, int M) {
    extern __shared__ char smem[];
    __nv_bfloat16* sAh = (__nv_bfloat16*)(smem + SM_AH);
    __nv_bfloat16* sAl = (__nv_bfloat16*)(smem + SM_AL);
    __nv_bfloat16* sBh = (__nv_bfloat16*)(smem + SM_BH);
    __nv_bfloat16* sBl = (__nv_bfloat16*)(smem + SM_BL);

    int tid = threadIdx.x;
    int lane = tid & 31;
    int wid = tid >> 5;
    int wm = wid & 1;        // 2 groups of 32 M-rows
    int wn = wid >> 1;       // 4 groups of 32 N-cols
    int row0 = blockIdx.x * 64;

    // A tile: 64 rows x 128 cols fp32 -> bf16 hi/lo split
#pragma unroll
    for (int i = 0; i < 8; i++) {
        int f = tid + 256 * i;          // 0..2047 float4 slots
        int row = f >> 5;
        int c4 = f & 31;
        float4 v = make_float4(0.f, 0.f, 0.f, 0.f);
        if (row0 + row < M)
            v = *(const float4*)&A[(long long)(row0 + row) * DD + c4 * 4];
        __nv_bfloat16 h0 = __float2bfloat16(v.x), l0 = __float2bfloat16(v.x - __bfloat162float(h0));
        __nv_bfloat16 h1 = __float2bfloat16(v.y), l1 = __float2bfloat16(v.y - __bfloat162float(h1));
        __nv_bfloat16 h2 = __float2bfloat16(v.z), l2 = __float2bfloat16(v.z - __bfloat162float(h2));
        __nv_bfloat16 h3 = __float2bfloat16(v.w), l3 = __float2bfloat16(v.w - __bfloat162float(h3));
        __nv_bfloat162* ph = (__nv_bfloat162*)&sAh[row * ASTR + c4 * 4];
        __nv_bfloat162* pl = (__nv_bfloat162*)&sAl[row * ASTR + c4 * 4];
        ph[0] = __nv_bfloat162(h0, h1); ph[1] = __nv_bfloat162(h2, h3);
        pl[0] = __nv_bfloat162(l0, l1); pl[1] = __nv_bfloat162(l2, l3);
    }
    // B tiles: [n][k] pre-split bf16
#pragma unroll
    for (int i = 0; i < 8; i++) {
        int f = tid + 256 * i;          // 0..2047 uint4 slots
        int row = f >> 4;
        int u4 = f & 15;
        *(uint4*)&sBh[row * ASTR + u4 * 8] = *(const uint4*)&Whi[row * DD + u4 * 8];
        *(uint4*)&sBl[row * ASTR + u4 * 8] = *(const uint4*)&Wlo[row * DD + u4 * 8];
    }
    __syncthreads();

    float acc[2][4][4];
#pragma unroll
    for (int ma = 0; ma < 2; ma++)
#pragma unroll
        for (int na = 0; na < 4; na++)
#pragma unroll
            for (int q = 0; q < 4; q++) acc[ma][na][q] = 0.0f;

    int arow = wm * 32 + (lane & 15);
    int acol_half = (lane >> 4) * 8;
    int brow = wn * 32 + (lane & 7);
    int bcol_half = ((lane >> 3) & 1) * 8;

    for (int k0 = 0; k0 < 128; k0 += 16) {
        uint32_t ah[2][4], al[2][4];
#pragma unroll
        for (int ma = 0; ma < 2; ma++) {
            uint32_t off = (uint32_t)((arow + ma * 16) * ASTR + k0 + acol_half) * 2;
            ldmat_x4(ah[ma], smem_u32(smem + SM_AH) + off);
            ldmat_x4(al[ma], smem_u32(smem + SM_AL) + off);
        }
        uint32_t bh[4][2], bl[4][2];
#pragma unroll
        for (int na = 0; na < 4; na++) {
            uint32_t off = (uint32_t)((brow + na * 8) * ASTR + k0 + bcol_half) * 2;
            ldmat_x2(bh[na], smem_u32(smem + SM_BH) + off);
            ldmat_x2(bl[na], smem_u32(smem + SM_BL) + off);
        }
#pragma unroll
        for (int ma = 0; ma < 2; ma++)
#pragma unroll
            for (int na = 0; na < 4; na++) {
                mma_bf16(acc[ma][na], ah[ma], bh[na]);
                mma_bf16(acc[ma][na], ah[ma], bl[na]);
                mma_bf16(acc[ma][na], al[ma], bh[na]);
            }
    }

    int gr = lane >> 2;
    int tg = lane & 3;
#pragma unroll
    for (int ma = 0; ma < 2; ma++) {
        int r0 = row0 + wm * 32 + ma * 16 + gr;
        int r1 = r0 + 8;
#pragma unroll
        for (int na = 0; na < 4; na++) {
            int col = wn * 32 + na * 8 + tg * 2;
            if (r0 < M)
                *(float2*)&C[(long long)r0 * DD + col] = make_float2(acc[ma][na][0], acc[ma][na][1]);
            if (r1 < M)
                *(float2*)&C[(long long)r1 * DD + col] = make_float2(acc[ma][na][2], acc[ma][na][3]);
        }
    }
}

// ---------------- gather aggregation (no atomics, prefetched) ----------------
__global__ void gather_kernel(const float* __restrict__ hw, const float* __restrict__ bias,
                              float* __restrict__ hout, int N) {
    int gwarp = (blockIdx.x * blockDim.x + threadIdx.x) >> 5;
    int lane = threadIdx.x & 31;
    if (gwarp >= N) return;
    const float4* hw4 = (const float4*)hw;
    int s = g_rowstart[gwarp];
    int e = g_rowstart[gwarp + 1];
    float sf = g_self[gwarp];
    float4 v = hw4[(long long)gwarp * 32 + lane];
    float4 acc = make_float4(sf * v.x, sf * v.y, sf * v.z, sf * v.w);
    int src_n = 0; float w_n = 0.0f;
    if (s < e) { src_n = g_csrc[s]; w_n = g_cw[s]; }
    for (int j = s; j < e; j++) {
        int src = src_n; float w = w_n;
        if (j + 1 < e) { src_n = g_csrc[j + 1]; w_n = g_cw[j + 1]; }
        float4 u = hw4[(long long)src * 32 + lane];
        acc.x = fmaf(w, u.x, acc.x);
        acc.y = fmaf(w, u.y, acc.y);
        acc.z = fmaf(w, u.z, acc.z);
        acc.w = fmaf(w, u.w, acc.w);
    }
    float4 b = *(const float4*)&bias[lane * 4];
    acc.x = fmaxf(acc.x + b.x, 0.0f);
    acc.y = fmaxf(acc.y + b.y, 0.0f);
    acc.z = fmaxf(acc.z + b.z, 0.0f);
    acc.w = fmaxf(acc.w + b.w, 0.0f);
    ((float4*)hout)[(long long)gwarp * 32 + lane] = acc;
}

// ---------------- segmented pooling (batch is sorted) ----------------
__global__ void zero_pool_kernel(int n) {
    int i = blockIdx.x * blockDim.x + threadIdx.x;
    if (i < n) g_pool[i] = 0.0f;
}

__global__ void pool_seg_kernel(const void* __restrict__ batch, int N) {
    int col = threadIdx.x;
    int n0 = blockIdx.x * 128;
    int n1 = min(n0 + 128, N);
    if (n0 >= N) return;
    float acc = 0.0f;
    int cur = (int)idx_at(batch, n0);
    for (int n = n0; n < n1; n++) {
        int b = (int)idx_at(batch, n);
        if (b != cur) {
            atomicAdd(&g_pool[cur * DD + col], acc);
            acc = 0.0f;
            cur = b;
        }
        acc += g_h[(long long)n * DD + col];
    }
    atomicAdd(&g_pool[cur * DD + col], acc);
}

// ---------------- fused MLP head ----------------
__global__ void mlp_fused_kernel(const float* __restrict__ W1, const float* __restrict__ b1,
                                 const float* __restrict__ W2, const float* __restrict__ b2,
                                 const float* __restrict__ W3, const float* __restrict__ b3,
                                 float* __restrict__ out) {
    __shared__ float a1[DD], t1[DD], t2[64];
    int g = blockIdx.x;
    int tid = threadIdx.x;
    a1[tid] = g_pool[g * DD + tid];
    __syncthreads();
    {
        float s = b1[tid];
#pragma unroll 8
        for (int k = 0; k < DD; k++) s = fmaf(a1[k], W1[k * DD + tid], s);
        t1[tid] = fmaxf(s, 0.0f);
    }
    __syncthreads();
    if (tid < 64) {
        float s = b2[tid];
#pragma unroll 8
        for (int k = 0; k < DD; k++) s = fmaf(t1[k], W2[k * 64 + tid], s);
        t2[tid] = fmaxf(s, 0.0f);
    }
    __syncthreads();
    if (tid < 10) {
        float s = b3[tid];
#pragma unroll 8
        for (int k = 0; k < 64; k++) s = fmaf(t2[k], W3[k * 10 + tid], s);
        out[g * 10 + tid] = s;
    }
}

// ---------------- launch (single stream, serial) ----------------
extern "C" void kernel_launch(void* const* d_in, const int* in_sizes, int n_in,
                              void* d_out, int out_size) {
    const float* x      = (const float*)d_in[0];
    const void*  ei     = d_in[1];
    const void*  batch  = d_in[2];
    const float* W_conv = (const float*)d_in[3];
    const float* b_conv = (const float*)d_in[4];
    const float* W1 = (const float*)d_in[5];
    const float* b1 = (const float*)d_in[6];
    const float* W2 = (const float*)d_in[7];
    const float* b2 = (const float*)d_in[8];
    const float* W3 = (const float*)d_in[9];
    const float* b3 = (const float*)d_in[10];

    int N = in_sizes[0] / DD;
    int E = in_sizes[1] / 2;
    int n_layers = in_sizes[3] / (DD * DD);
    int G = out_size / 10;

    static bool init_done = false;
    static float* p_h = nullptr;
    static float* p_hw = nullptr;
    static __nv_bfloat16* p_wbf = nullptr;
    if (!init_done) {
        cudaFuncSetAttribute(gemm_mma_kernel, cudaFuncAttributeMaxDynamicSharedMemorySize, SM_TOTAL);
        cudaGetSymbolAddress((void**)&p_h, g_h);
        cudaGetSymbolAddress((void**)&p_hw, g_hw);
        cudaGetSymbolAddress((void**)&p_wbf, g_Wbf);
        init_done = true;
    }

    int gemm_grid = (N + 63) / 64;
    int gather_grid = (N + 7) / 8;

    // Ordered so gemm0 is the 4th launch (ncu -s 5 slot lands on it).
    detect_kernel<<<1, 32>>>((const unsigned int*)ei);                       // 1
    zero_hist_kernel<<<(N + 255) / 256, 256>>>(N);                           // 2
    prep_w_kernel<<<(n_layers * DD * DD + 255) / 256, 256>>>(W_conv, n_layers); // 3
    gemm_mma_kernel<<<gemm_grid, 256, SM_TOTAL>>>(x, p_wbf, p_wbf + DD * DD, p_hw, N); // 4 <- profiled
    hist_kernel<<<(E + 255) / 256, 256>>>(ei, E);
    dinv_kernel<<<(N + 255) / 256, 256>>>(N);
    scan_kernel<<<1, 1024>>>(N, E);
    fill_kernel<<<(E + 255) / 256, 256>>>(ei, E);

    gather_kernel<<<gather_grid, 256>>>(p_hw, b_conv, p_h, N);
    for (int l = 1; l < n_layers; l++) {
        const __nv_bfloat16* whi = p_wbf + (long long)l * 2 * DD * DD;
        const __nv_bfloat16* wlo = whi + DD * DD;
        gemm_mma_kernel<<<gemm_grid, 256, SM_TOTAL>>>(p_h, whi, wlo, p_hw, N);
        gather_kernel<<<gather_grid, 256>>>(p_hw, b_conv + l * DD, p_h, N);
    }

    zero_pool_kernel<<<(G * DD + 255) / 256, 256>>>(G * DD);
    pool_seg_kernel<<<(N + 127) / 128, 128>>>(batch, N);
    mlp_fused_kernel<<<G, 128>>>(W1, b1, W2, b2, W3, b3, (float*)d_out);
}

// round 8
// speedup vs baseline: 1.2023x; 1.2023x over previous
#include <cuda_runtime.h>
#include <cuda_bf16.h>
#include <cstdint>

// GCN forward: 4x (mma.sync bf16x3 GEMM + CSR-gather) + atomic pool + fused MLP.
// Stream fork: CSR build chain overlaps prep_w + gemm0 (measured +20us win).
// GEMM tile 128x128, 1 CTA/SM (measured best: 24.8us/layer).

#define DD 128
#define NMAX 50000
#define EMAX 800000
#define GMAX 512

__device__ int   g_is64;
__device__ float g_h[NMAX * DD];
__device__ float g_hw[NMAX * DD];
__device__ float g_dinv[NMAX];
__device__ float g_self[NMAX];
__device__ int   g_hist[NMAX];
__device__ int   g_rowstart[NMAX + 1];
__device__ int   g_cursor[NMAX];
__device__ int   g_csrc[EMAX];
__device__ float g_cw[EMAX];
__device__ float g_pool[GMAX * DD];
__device__ __nv_bfloat16 g_Wbf[4][2][DD * DD];

__device__ __forceinline__ uint32_t smem_u32(const void* p) {
    return (uint32_t)__cvta_generic_to_shared(p);
}
__device__ __forceinline__ long long idx_at(const void* p, long long i) {
    if (g_is64) return ((const long long*)p)[i];
    return (long long)((const int*)p)[i];
}

__global__ void detect_kernel(const unsigned int* __restrict__ p) {
    if (threadIdx.x == 0 && blockIdx.x == 0) {
        int is64 = 1;
        for (int k = 1; k <= 15; k += 2)
            if (p[k] != 0u) { is64 = 0; break; }
        g_is64 = is64;
    }
}

__global__ void zero_hist_kernel(int n) {
    int i = blockIdx.x * blockDim.x + threadIdx.x;
    if (i < n) g_hist[i] = 0;
}

__global__ void hist_kernel(const void* __restrict__ ei, int E) {
    int e = blockIdx.x * blockDim.x + threadIdx.x;
    if (e < E) {
        int c = (int)idx_at(ei, (long long)E + e);
        atomicAdd(&g_hist[c], 1);
    }
}

__global__ void dinv_kernel(int n) {
    int i = blockIdx.x * blockDim.x + threadIdx.x;
    if (i < n) {
        float deg = (float)g_hist[i] + 1.0f;
        g_dinv[i] = rsqrtf(deg);
        g_self[i] = 1.0f / deg;
    }
}

__global__ void scan_kernel(int n, int E) {
    __shared__ int sums[1024];
    int t = threadIdx.x;
    int chunk = (n + 1023) / 1024;
    int b0 = t * chunk;
    int b1 = min(b0 + chunk, n);
    int s = 0;
    for (int i = b0; i < b1; i++) s += g_hist[i];
    sums[t] = s;
    __syncthreads();
    for (int off = 1; off < 1024; off <<= 1) {
        int v = (t >= off) ? sums[t - off] : 0;
        __syncthreads();
        sums[t] += v;
        __syncthreads();
    }
    int run = (t == 0) ? 0 : sums[t - 1];
    for (int i = b0; i < b1; i++) {
        g_rowstart[i] = run;
        g_cursor[i] = run;
        run += g_hist[i];
    }
    if (t == 0) g_rowstart[n] = E;
}

__global__ void fill_kernel(const void* __restrict__ ei, int E) {
    int e = blockIdx.x * blockDim.x + threadIdx.x;
    if (e < E) {
        int r = (int)idx_at(ei, e);
        int c = (int)idx_at(ei, (long long)E + e);
        int pos = atomicAdd(&g_cursor[c], 1);
        g_csrc[pos] = r;
        g_cw[pos] = g_dinv[r] * g_dinv[c];
    }
}

__global__ void prep_w_kernel(const float* __restrict__ W_conv, int n_layers) {
    int idx = blockIdx.x * blockDim.x + threadIdx.x;
    int total = n_layers * DD * DD;
    if (idx >= total) return;
    int l = idx / (DD * DD);
    int rem = idx % (DD * DD);
    int k = rem / DD;
    int n = rem % DD;
    float w = W_conv[(long long)l * DD * DD + k * DD + n];
    __nv_bfloat16 hi = __float2bfloat16(w);
    __nv_bfloat16 lo = __float2bfloat16(w - __bfloat162float(hi));
    g_Wbf[l][0][n * DD + k] = hi;
    g_Wbf[l][1][n * DD + k] = lo;
}

// ---------------- mma.sync bf16x3 GEMM: tile 128(M) x 128(N), K=128 ----------------
#define ASTR 136
#define TILE_BYTES (128 * ASTR * 2)
#define SM_AH 0
#define SM_AL (TILE_BYTES)
#define SM_BH (2 * TILE_BYTES)
#define SM_BL (3 * TILE_BYTES)
#define SM_TOTAL (4 * TILE_BYTES)     // 139264

__device__ __forceinline__ void ldmat_x4(uint32_t* r, uint32_t addr) {
    asm volatile("ldmatrix.sync.aligned.m8n8.x4.shared.b16 {%0,%1,%2,%3}, [%4];"
                 : "=r"(r[0]), "=r"(r[1]), "=r"(r[2]), "=r"(r[3]) : "r"(addr));
}
__device__ __forceinline__ void ldmat_x2(uint32_t* r, uint32_t addr) {
    asm volatile("ldmatrix.sync.aligned.m8n8.x2.shared.b16 {%0,%1}, [%2];"
                 : "=r"(r[0]), "=r"(r[1]) : "r"(addr));
}
__device__ __forceinline__ void mma_bf16(float* c, const uint32_t* a, const uint32_t* b) {
    asm volatile("mma.sync.aligned.m16n8k16.row.col.f32.bf16.bf16.f32 "
                 "{%0,%1,%2,%3}, {%4,%5,%6,%7}, {%8,%9}, {%0,%1,%2,%3};"
                 : "+f"(c[0]), "+f"(c[1]), "+f"(c[2]), "+f"(c[3])
                 : "r"(a[0]), "r"(a[1]), "r"(a[2]), "r"(a[3]), "r"(b[0]), "r"(b[1]));
}

__global__ void __launch_bounds__(256, 1)
gemm_mma_kernel(const float* __restrict__ A,
                const __nv_bfloat16* __restrict__ Whi,
                const __nv_bfloat16* __restrict__ Wlo,
                float* __restrict__ C, int M) {
    extern __shared__ char smem[];
    __nv_bfloat16* sAh = (__nv_bfloat16*)(smem + SM_AH);
    __nv_bfloat16* sAl = (__nv_bfloat16*)(smem + SM_AL);
    __nv_bfloat16* sBh = (__nv_bfloat16*)(smem + SM_BH);
    __nv_bfloat16* sBl = (__nv_bfloat16*)(smem + SM_BL);

    int tid = threadIdx.x;
    int lane = tid & 31;
    int wid = tid >> 5;
    int wm = wid & 3;
    int wn = wid >> 2;
    int row0 = blockIdx.x * 128;

#pragma unroll
    for (int i = 0; i < 16; i++) {
        int f = tid + 256 * i;
        int row = f >> 5;
        int c4 = f & 31;
        float4 v = make_float4(0.f, 0.f, 0.f, 0.f);
        if (row0 + row < M)
            v = *(const float4*)&A[(long long)(row0 + row) * DD + c4 * 4];
        __nv_bfloat16 h0 = __float2bfloat16(v.x), l0 = __float2bfloat16(v.x - __bfloat162float(h0));
        __nv_bfloat16 h1 = __float2bfloat16(v.y), l1 = __float2bfloat16(v.y - __bfloat162float(h1));
        __nv_bfloat16 h2 = __float2bfloat16(v.z), l2 = __float2bfloat16(v.z - __bfloat162float(h2));
        __nv_bfloat16 h3 = __float2bfloat16(v.w), l3 = __float2bfloat16(v.w - __bfloat162float(h3));
        __nv_bfloat162* ph = (__nv_bfloat162*)&sAh[row * ASTR + c4 * 4];
        __nv_bfloat162* pl = (__nv_bfloat162*)&sAl[row * ASTR + c4 * 4];
        ph[0] = __nv_bfloat162(h0, h1); ph[1] = __nv_bfloat162(h2, h3);
        pl[0] = __nv_bfloat162(l0, l1); pl[1] = __nv_bfloat162(l2, l3);
    }
#pragma unroll
    for (int i = 0; i < 8; i++) {
        int f = tid + 256 * i;
        int row = f >> 4;
        int u4 = f & 15;
        *(uint4*)&sBh[row * ASTR + u4 * 8] = *(const uint4*)&Whi[row * DD + u4 * 8];
        *(uint4*)&sBl[row * ASTR + u4 * 8] = *(const uint4*)&Wlo[row * DD + u4 * 8];
    }
    __syncthreads();

    float acc[2][8][4];
#pragma unroll
    for (int ma = 0; ma < 2; ma++)
#pragma unroll
        for (int na = 0; na < 8; na++)
#pragma unroll
            for (int q = 0; q < 4; q++) acc[ma][na][q] = 0.0f;

    int arow = wm * 32 + (lane & 15);
    int acol_half = (lane >> 4) * 8;
    int brow = wn * 64 + (lane & 7);
    int bcol_half = ((lane >> 3) & 1) * 8;

    for (int k0 = 0; k0 < 128; k0 += 16) {
        uint32_t ah[2][4], al[2][4];
#pragma unroll
        for (int ma = 0; ma < 2; ma++) {
            uint32_t off = (uint32_t)((arow + ma * 16) * ASTR + k0 + acol_half) * 2;
            ldmat_x4(ah[ma], smem_u32(smem + SM_AH) + off);
            ldmat_x4(al[ma], smem_u32(smem + SM_AL) + off);
        }
        uint32_t bh[8][2], bl[8][2];
#pragma unroll
        for (int na = 0; na < 8; na++) {
            uint32_t off = (uint32_t)((brow + na * 8) * ASTR + k0 + bcol_half) * 2;
            ldmat_x2(bh[na], smem_u32(smem + SM_BH) + off);
            ldmat_x2(bl[na], smem_u32(smem + SM_BL) + off);
        }
#pragma unroll
        for (int ma = 0; ma < 2; ma++)
#pragma unroll
            for (int na = 0; na < 8; na++) {
                mma_bf16(acc[ma][na], ah[ma], bh[na]);
                mma_bf16(acc[ma][na], ah[ma], bl[na]);
                mma_bf16(acc[ma][na], al[ma], bh[na]);
            }
    }

    int gr = lane >> 2;
    int tg = lane & 3;
#pragma unroll
    for (int ma = 0; ma < 2; ma++) {
        int r0 = row0 + wm * 32 + ma * 16 + gr;
        int r1 = r0 + 8;
#pragma unroll
        for (int na = 0; na < 8; na++) {
            int col = wn * 64 + na * 8 + tg * 2;
            if (r0 < M)
                *(float2*)&C[(long long)r0 * DD + col] = make_float2(acc[ma][na][0], acc[ma][na][1]);
            if (r1 < M)
                *(float2*)&C[(long long)r1 * DD + col] = make_float2(acc[ma][na][2], acc[ma][na][3]);
        }
    }
}

// ---------------- gather aggregation (no atomics; R3 plain loop) ----------------
__global__ void gather_kernel(const float* __restrict__ hw, const float* __restrict__ bias,
                              float* __restrict__ hout, int N) {
    int gwarp = (blockIdx.x * blockDim.x + threadIdx.x) >> 5;
    int lane = threadIdx.x & 31;
    if (gwarp >= N) return;
    const float4* hw4 = (const float4*)hw;
    int s = g_rowstart[gwarp];
    int e = g_rowstart[gwarp + 1];
    float sf = g_self[gwarp];
    float4 v = hw4[(long long)gwarp * 32 + lane];
    float4 acc = make_float4(sf * v.x, sf * v.y, sf * v.z, sf * v.w);
    for (int j = s; j < e; j++) {
        int src = g_csrc[j];
        float w = g_cw[j];
        float4 u = hw4[(long long)src * 32 + lane];
        acc.x = fmaf(w, u.x, acc.x);
        acc.y = fmaf(w, u.y, acc.y);
        acc.z = fmaf(w, u.z, acc.z);
        acc.w = fmaf(w, u.w, acc.w);
    }
    float4 b = *(const float4*)&bias[lane * 4];
    acc.x = fmaxf(acc.x + b.x, 0.0f);
    acc.y = fmaxf(acc.y + b.y, 0.0f);
    acc.z = fmaxf(acc.z + b.z, 0.0f);
    acc.w = fmaxf(acc.w + b.w, 0.0f);
    ((float4*)hout)[(long long)gwarp * 32 + lane] = acc;
}

// ---------------- pooling (R3 atomic version) ----------------
__global__ void zero_pool_kernel(int n) {
    int i = blockIdx.x * blockDim.x + threadIdx.x;
    if (i < n) g_pool[i] = 0.0f;
}

__global__ void pool_kernel(const void* __restrict__ batch, int N) {
    int t = blockIdx.x * blockDim.x + threadIdx.x;
    int node = t >> 5;
    int lane = t & 31;
    if (node >= N) return;
    int gb = (int)idx_at(batch, node);
    float4 v = ((const float4*)g_h)[(long long)node * 32 + lane];
    float* base = &g_pool[gb * DD + lane * 4];
    atomicAdd(base + 0, v.x);
    atomicAdd(base + 1, v.y);
    atomicAdd(base + 2, v.z);
    atomicAdd(base + 3, v.w);
}

// ---------------- fused MLP head ----------------
__global__ void mlp_fused_kernel(const float* __restrict__ W1, const float* __restrict__ b1,
                                 const float* __restrict__ W2, const float* __restrict__ b2,
                                 const float* __restrict__ W3, const float* __restrict__ b3,
                                 float* __restrict__ out) {
    __shared__ float a1[DD], t1[DD], t2[64];
    int g = blockIdx.x;
    int tid = threadIdx.x;
    a1[tid] = g_pool[g * DD + tid];
    __syncthreads();
    {
        float s = b1[tid];
#pragma unroll 8
        for (int k = 0; k < DD; k++) s = fmaf(a1[k], W1[k * DD + tid], s);
        t1[tid] = fmaxf(s, 0.0f);
    }
    __syncthreads();
    if (tid < 64) {
        float s = b2[tid];
#pragma unroll 8
        for (int k = 0; k < DD; k++) s = fmaf(t1[k], W2[k * 64 + tid], s);
        t2[tid] = fmaxf(s, 0.0f);
    }
    __syncthreads();
    if (tid < 10) {
        float s = b3[tid];
#pragma unroll 8
        for (int k = 0; k < 64; k++) s = fmaf(t2[k], W3[k * 10 + tid], s);
        out[g * 10 + tid] = s;
    }
}

// ---------------- launch ----------------
extern "C" void kernel_launch(void* const* d_in, const int* in_sizes, int n_in,
                              void* d_out, int out_size) {
    const float* x      = (const float*)d_in[0];
    const void*  ei     = d_in[1];
    const void*  batch  = d_in[2];
    const float* W_conv = (const float*)d_in[3];
    const float* b_conv = (const float*)d_in[4];
    const float* W1 = (const float*)d_in[5];
    const float* b1 = (const float*)d_in[6];
    const float* W2 = (const float*)d_in[7];
    const float* b2 = (const float*)d_in[8];
    const float* W3 = (const float*)d_in[9];
    const float* b3 = (const float*)d_in[10];

    int N = in_sizes[0] / DD;
    int E = in_sizes[1] / 2;
    int n_layers = in_sizes[3] / (DD * DD);
    int G = out_size / 10;

    static bool init_done = false;
    static cudaStream_t s2;
    static cudaEvent_t ev_fork, ev_join;
    static float* p_h = nullptr;
    static float* p_hw = nullptr;
    static __nv_bfloat16* p_wbf = nullptr;
    if (!init_done) {
        cudaFuncSetAttribute(gemm_mma_kernel, cudaFuncAttributeMaxDynamicSharedMemorySize, SM_TOTAL);
        cudaStreamCreateWithFlags(&s2, cudaStreamNonBlocking);
        cudaEventCreateWithFlags(&ev_fork, cudaEventDisableTiming);
        cudaEventCreateWithFlags(&ev_join, cudaEventDisableTiming);
        cudaGetSymbolAddress((void**)&p_h, g_h);
        cudaGetSymbolAddress((void**)&p_hw, g_hw);
        cudaGetSymbolAddress((void**)&p_wbf, g_Wbf);
        init_done = true;
    }

    int gemm_grid = (N + 127) / 128;
    int gather_grid = (N + 7) / 8;

    // Fork: stream0 = CSR build chain, s2 = prep_w + gemm0.
    // gemm0 is the 4th submitted kernel -> lands in the ncu -s 5 slot.
    detect_kernel<<<1, 32>>>((const unsigned int*)ei);                          // 1
    cudaEventRecord(ev_fork, 0);
    cudaStreamWaitEvent(s2, ev_fork, 0);
    prep_w_kernel<<<(n_layers * DD * DD + 255) / 256, 256, 0, s2>>>(W_conv, n_layers); // 2
    zero_hist_kernel<<<(N + 255) / 256, 256>>>(N);                              // 3
    gemm_mma_kernel<<<gemm_grid, 256, SM_TOTAL, s2>>>(x, p_wbf, p_wbf + DD * DD, p_hw, N); // 4 <- profiled
    hist_kernel<<<(E + 255) / 256, 256>>>(ei, E);
    dinv_kernel<<<(N + 255) / 256, 256>>>(N);
    scan_kernel<<<1, 1024>>>(N, E);
    fill_kernel<<<(E + 255) / 256, 256>>>(ei, E);
    cudaEventRecord(ev_join, s2);
    cudaStreamWaitEvent(0, ev_join, 0);

    gather_kernel<<<gather_grid, 256>>>(p_hw, b_conv, p_h, N);
    for (int l = 1; l < n_layers; l++) {
        const __nv_bfloat16* whi = p_wbf + (long long)l * 2 * DD * DD;
        const __nv_bfloat16* wlo = whi + DD * DD;
        gemm_mma_kernel<<<gemm_grid, 256, SM_TOTAL>>>(p_h, whi, wlo, p_hw, N);
        gather_kernel<<<gather_grid, 256>>>(p_hw, b_conv + l * DD, p_h, N);
    }

    zero_pool_kernel<<<(G * DD + 255) / 256, 256>>>(G * DD);
    pool_kernel<<<(N * 32 + 255) / 256, 256>>>(batch, N);
    mlp_fused_kernel<<<G, 128>>>(W1, b1, W2, b2, W3, b3, (float*)d_out);
}